// round 4
// baseline (speedup 1.0000x reference)
#include <cuda_runtime.h>
#include <cstdint>

#define VOCAB 50000
#define EMB   32
#define HID   64
#define H4    256
#define NCLS  3
#define BSZ   512
#define TLEN  512
#define FULL  0xffffffffu

// 51.2MB scratch: precomputed emb @ Wk + bias, per vocab entry (256 floats each)
__device__ float g_table[(size_t)VOCAB * H4];

// ---------- packed f32x2 helpers (sm_103a FFMA2 path, PTX-only) ----------
__device__ __forceinline__ unsigned long long pack2(float lo, float hi) {
    unsigned long long r;
    asm("mov.b64 %0, {%1, %2};" : "=l"(r) : "f"(lo), "f"(hi));
    return r;
}
__device__ __forceinline__ float2 unpack2(unsigned long long v) {
    float2 f;
    asm("mov.b64 {%0, %1}, %2;" : "=f"(f.x), "=f"(f.y) : "l"(v));
    return f;
}
#define FMA2(acc, a, b) \
    asm("fma.rn.f32x2 %0, %1, %2, %0;" : "+l"(acc) : "l"(a), "l"(b))
#define ADD2(d, a, b) \
    asm("add.rn.f32x2 %0, %1, %2;" : "=l"(d) : "l"(a), "l"(b))

__device__ __forceinline__ float sigf(float x) {
    float t = __expf(-x);
    return 1.0f / (1.0f + t);
}
__device__ __forceinline__ float tanh_acc(float x) {
    float a  = fabsf(x);
    float t  = __expf(-2.0f * a);
    float r  = (1.0f - t) / (1.0f + t);
    return copysignf(r, x);
}

// ---------- kernel 1: g_table[v][j] = sum_e emb[v][e]*Wk[e][j] + b[j] ----------
__global__ __launch_bounds__(256) void table_kernel(
    const float* __restrict__ emb, const float* __restrict__ Wk,
    const float* __restrict__ bias)
{
    __shared__ __align__(16) float sh_e[64 * EMB];  // 64 vocab rows staged
    const int j  = threadIdx.x;                     // output column 0..255
    const int v0 = blockIdx.x * 64;

    unsigned long long wk2[16];
#pragma unroll
    for (int m = 0; m < 16; m++)
        wk2[m] = pack2(Wk[(2 * m) * H4 + j], Wk[(2 * m + 1) * H4 + j]);
    const float bj = bias[j];

    const int nrows = min(64, VOCAB - v0);
    const float4* src = reinterpret_cast<const float4*>(emb + (size_t)v0 * EMB);
    float4* dst = reinterpret_cast<float4*>(sh_e);
    for (int i = j; i < nrows * (EMB / 4); i += 256) dst[i] = src[i];
    __syncthreads();

    for (int r = 0; r < nrows; r++) {
        const ulonglong2* ev = reinterpret_cast<const ulonglong2*>(sh_e + r * EMB);
        unsigned long long a0 = 0ull, a1 = 0ull;
#pragma unroll
        for (int m = 0; m < 4; m++) {
            ulonglong2 p = ev[2 * m];
            ulonglong2 q = ev[2 * m + 1];
            FMA2(a0, p.x, wk2[4 * m + 0]);
            FMA2(a1, p.y, wk2[4 * m + 1]);
            FMA2(a0, q.x, wk2[4 * m + 2]);
            FMA2(a1, q.y, wk2[4 * m + 3]);
        }
        unsigned long long s;
        ADD2(s, a0, a1);
        float2 f = unpack2(s);
        g_table[(size_t)(v0 + r) * H4 + j] = bj + f.x + f.y;
    }
}

// ---------- kernel 2: recurrent LSTM, 2 batch rows per CTA ----------
// Warp-aligned gate layout: warp w owns units 8w..8w+7; lane l handles
// column jcol = (l&3)*64 + (8w + l>>4gates). Gates computed in-warp via
// shuffle (z never hits smem). h double-buffered in smem; ONE barrier/step.
__global__ __launch_bounds__(256, 2) void lstm_kernel(
    const int*   __restrict__ tokens,
    const float* __restrict__ Wr,
    const float* __restrict__ Wd,
    const float* __restrict__ bd,
    float*       __restrict__ out)
{
    __shared__ __align__(16) float sh_h[2][2][HID];  // [buf][batch][unit]
    __shared__ int sh_tok[2][TLEN];

    const int j      = threadIdx.x;
    const int w      = j >> 5;
    const int l      = j & 31;
    const int unit   = 8 * w + (l >> 2);   // 0..63
    const int gate   = l & 3;              // i,f,g,o
    const int jcol   = gate * 64 + unit;   // this thread's gate column
    const int s_mine = (l >> 1) & 1;       // batch this lane gates
    const int b0     = blockIdx.x * 2;

    // stage this CTA's token rows
    for (int i = j; i < 2 * TLEN; i += 256) {
        int s = i >> 9, t = i & (TLEN - 1);
        sh_tok[s][t] = tokens[(size_t)(b0 + s) * TLEN + t];
    }

    // Wr column jcol, packed over k: wr2[m] = (Wr[2m][jcol], Wr[2m+1][jcol])
    unsigned long long wr2[32];
#pragma unroll
    for (int m = 0; m < 32; m++)
        wr2[m] = pack2(Wr[(2 * m) * H4 + jcol], Wr[(2 * m + 1) * H4 + jcol]);

    if (j < 2 * HID) sh_h[0][j >> 6][j & (HID - 1)] = 0.0f;
    float cst = 0.0f;  // cell state for (s_mine, unit); redundancy 2, deterministic
    __syncthreads();

    // prefetch xz for t=0
    float xzn0 = g_table[(size_t)sh_tok[0][0] * H4 + jcol];
    float xzn1 = g_table[(size_t)sh_tok[1][0] * H4 + jcol];

#pragma unroll 1
    for (int t = 0; t < TLEN; t++) {
        const float xz0 = xzn0, xz1 = xzn1;
        const int tn = (t < TLEN - 1) ? t + 1 : t;
        xzn0 = g_table[(size_t)sh_tok[0][tn] * H4 + jcol];
        xzn1 = g_table[(size_t)sh_tok[1][tn] * H4 + jcol];

        // z[s][jcol] = xz + h[s] . Wr[:,jcol]   (packed f32x2, 4 chains/batch)
        const float* hb = sh_h[t & 1][0];
        const ulonglong2* h0 = reinterpret_cast<const ulonglong2*>(hb);
        const ulonglong2* h1 = reinterpret_cast<const ulonglong2*>(hb + HID);
        unsigned long long a0 = 0ull, a1 = 0ull, a2 = 0ull, a3 = 0ull;
        unsigned long long c0 = 0ull, c1 = 0ull, c2 = 0ull, c3 = 0ull;
#pragma unroll
        for (int m = 0; m < 8; m++) {
            ulonglong2 p0 = h0[2 * m];
            ulonglong2 q0 = h0[2 * m + 1];
            ulonglong2 p1 = h1[2 * m];
            ulonglong2 q1 = h1[2 * m + 1];
            FMA2(a0, p0.x, wr2[4 * m + 0]);
            FMA2(a1, p0.y, wr2[4 * m + 1]);
            FMA2(a2, q0.x, wr2[4 * m + 2]);
            FMA2(a3, q0.y, wr2[4 * m + 3]);
            FMA2(c0, p1.x, wr2[4 * m + 0]);
            FMA2(c1, p1.y, wr2[4 * m + 1]);
            FMA2(c2, q1.x, wr2[4 * m + 2]);
            FMA2(c3, q1.y, wr2[4 * m + 3]);
        }
        float z0, z1;
        {
            unsigned long long t0, t1;
            ADD2(t0, a0, a1);
            ADD2(t1, a2, a3);
            ADD2(t0, t0, t1);
            float2 f = unpack2(t0);
            z0 = xz0 + f.x + f.y;
            ADD2(t0, c0, c1);
            ADD2(t1, c2, c3);
            ADD2(t0, t0, t1);
            float2 g = unpack2(t0);
            z1 = xz1 + g.x + g.y;
        }

        // in-warp gate gather: the 4 gate columns of `unit` live in lanes
        // base..base+3 of this warp
        const int base = l & ~3;
        const float zi0 = __shfl_sync(FULL, z0, base + 0);
        const float zi1 = __shfl_sync(FULL, z1, base + 0);
        const float zf0 = __shfl_sync(FULL, z0, base + 1);
        const float zf1 = __shfl_sync(FULL, z1, base + 1);
        const float zg0 = __shfl_sync(FULL, z0, base + 2);
        const float zg1 = __shfl_sync(FULL, z1, base + 2);
        const float zo0 = __shfl_sync(FULL, z0, base + 3);
        const float zo1 = __shfl_sync(FULL, z1, base + 3);

        const float zi = s_mine ? zi1 : zi0;
        const float zf = s_mine ? zf1 : zf0;
        const float zg = s_mine ? zg1 : zg0;
        const float zo = s_mine ? zo1 : zo0;

        const float ig = sigf(zi);
        const float fg = sigf(zf);
        const float og = sigf(zo);
        const float gg = tanh_acc(zg);
        cst = fg * cst + ig * gg;
        const float hv = og * tanh_acc(cst);

        if ((l & 1) == 0) sh_h[(t & 1) ^ 1][s_mine][unit] = hv;
        __syncthreads();
    }

    // final h is in buffer 0 (last write at t=511 targets (511&1)^1 = 0)
    if (j < 2) {
        const int s = j;
        float l0 = bd[0], l1 = bd[1], l2 = bd[2];
#pragma unroll 8
        for (int u = 0; u < HID; u++) {
            const float h = sh_h[0][s][u];
            l0 += h * Wd[u * NCLS + 0];
            l1 += h * Wd[u * NCLS + 1];
            l2 += h * Wd[u * NCLS + 2];
        }
        const float m  = fmaxf(l0, fmaxf(l1, l2));
        const float e0 = __expf(l0 - m);
        const float e1 = __expf(l1 - m);
        const float e2 = __expf(l2 - m);
        const float inv = 1.0f / (e0 + e1 + e2);
        float* o = out + (size_t)(b0 + s) * NCLS;
        o[0] = e0 * inv;
        o[1] = e1 * inv;
        o[2] = e2 * inv;
    }
}

extern "C" void kernel_launch(void* const* d_in, const int* in_sizes, int n_in,
                              void* d_out, int out_size)
{
    const int*   tokens = (const int*)  d_in[0];
    const float* emb    = (const float*)d_in[1];
    const float* Wk     = (const float*)d_in[2];
    const float* Wr     = (const float*)d_in[3];
    const float* b      = (const float*)d_in[4];
    const float* Wd     = (const float*)d_in[5];
    const float* bd     = (const float*)d_in[6];
    float* out = (float*)d_out;

    table_kernel<<<(VOCAB + 63) / 64, 256>>>(emb, Wk, b);
    lstm_kernel<<<BSZ / 2, 256>>>(tokens, Wr, Wd, bd, out);
}

// round 5
// speedup vs baseline: 1.2023x; 1.2023x over previous
#include <cuda_runtime.h>
#include <cstdint>

#define VOCAB 50000
#define EMB   32
#define HID   64
#define H4    256
#define NCLS  3
#define BSZ   512
#define TLEN  512

// 51.2MB scratch: precomputed emb @ Wk + bias, per vocab entry (256 floats each)
__device__ float g_table[(size_t)VOCAB * H4];

// ---------- packed f32x2 helpers (sm_103a FFMA2 path, PTX-only) ----------
__device__ __forceinline__ unsigned long long pack2(float lo, float hi) {
    unsigned long long r;
    asm("mov.b64 %0, {%1, %2};" : "=l"(r) : "f"(lo), "f"(hi));
    return r;
}
__device__ __forceinline__ float2 unpack2(unsigned long long v) {
    float2 f;
    asm("mov.b64 {%0, %1}, %2;" : "=f"(f.x), "=f"(f.y) : "l"(v));
    return f;
}
#define FMA2(acc, a, b) \
    asm("fma.rn.f32x2 %0, %1, %2, %0;" : "+l"(acc) : "l"(a), "l"(b))
#define ADD2(d, a, b) \
    asm("add.rn.f32x2 %0, %1, %2;" : "=l"(d) : "l"(a), "l"(b))

__device__ __forceinline__ float sigf(float x) {
    float t = __expf(-x);
    return __fdividef(1.0f, 1.0f + t);
}
__device__ __forceinline__ float tanh_acc(float x) {
    float a = fabsf(x);
    float t = __expf(-2.0f * a);
    float r = __fdividef(1.0f - t, 1.0f + t);
    return copysignf(r, x);
}

// ---------- kernel 1: g_table[v][j] = sum_e emb[v][e]*Wk[e][j] + b[j] ----------
__global__ __launch_bounds__(256) void table_kernel(
    const float* __restrict__ emb, const float* __restrict__ Wk,
    const float* __restrict__ bias)
{
    __shared__ __align__(16) float sh_e[64 * EMB];
    const int j  = threadIdx.x;
    const int v0 = blockIdx.x * 64;

    unsigned long long wk2[16];
#pragma unroll
    for (int m = 0; m < 16; m++)
        wk2[m] = pack2(Wk[(2 * m) * H4 + j], Wk[(2 * m + 1) * H4 + j]);
    const float bj = bias[j];

    const int nrows = min(64, VOCAB - v0);
    const float4* src = reinterpret_cast<const float4*>(emb + (size_t)v0 * EMB);
    float4* dst = reinterpret_cast<float4*>(sh_e);
    for (int i = j; i < nrows * (EMB / 4); i += 256) dst[i] = src[i];
    __syncthreads();

    for (int r = 0; r < nrows; r++) {
        const ulonglong2* ev = reinterpret_cast<const ulonglong2*>(sh_e + r * EMB);
        unsigned long long a0 = 0ull, a1 = 0ull;
#pragma unroll
        for (int m = 0; m < 4; m++) {
            ulonglong2 p = ev[2 * m];
            ulonglong2 q = ev[2 * m + 1];
            FMA2(a0, p.x, wk2[4 * m + 0]);
            FMA2(a1, p.y, wk2[4 * m + 1]);
            FMA2(a0, q.x, wk2[4 * m + 2]);
            FMA2(a1, q.y, wk2[4 * m + 3]);
        }
        unsigned long long s;
        ADD2(s, a0, a1);
        float2 f = unpack2(s);
        g_table[(size_t)(v0 + r) * H4 + j] = bj + f.x + f.y;
    }
}

// ---------- kernel 2: recurrent LSTM, 4 batch rows per CTA, grid 128 ----------
// One CTA per SM (grid 128 <= 148, single balanced wave). Thread j owns gate
// column j for ALL 4 batches (128 FMA2/step). Gate phase: thread j handles
// (s=j>>6, u=j&63) -- all 256 threads busy. h double-buffered; 2 barriers/step.
__global__ __launch_bounds__(256, 1) void lstm_kernel(
    const int*   __restrict__ tokens,
    const float* __restrict__ Wr,
    const float* __restrict__ Wd,
    const float* __restrict__ bd,
    float*       __restrict__ out)
{
    __shared__ __align__(16) float sh_h[2][4][HID];  // [buf][batch][unit]
    __shared__ float sh_z[4][H4];
    __shared__ int   sh_tok[4][TLEN];

    const int j    = threadIdx.x;     // gate column 0..255
    const int su_s = j >> 6;          // gate-phase batch
    const int su_u = j & (HID - 1);   // gate-phase unit
    const int b0   = blockIdx.x * 4;

    // stage this CTA's 4 token rows
    for (int i = j; i < 4 * TLEN; i += 256) {
        int s = i >> 9, t = i & (TLEN - 1);
        sh_tok[s][t] = tokens[(size_t)(b0 + s) * TLEN + t];
    }

    // Wr column j, packed over k: wr2[m] = (Wr[2m][j], Wr[2m+1][j])  (64 regs)
    unsigned long long wr2[32];
#pragma unroll
    for (int m = 0; m < 32; m++)
        wr2[m] = pack2(Wr[(2 * m) * H4 + j], Wr[(2 * m + 1) * H4 + j]);

    sh_h[0][su_s][su_u] = 0.0f;   // 256 threads cover [4][64] exactly
    float cst = 0.0f;             // cell state for (su_s, su_u)
    __syncthreads();

    // prefetch xz for t=0 (table is L2-resident)
    float xzn0 = g_table[(size_t)sh_tok[0][0] * H4 + j];
    float xzn1 = g_table[(size_t)sh_tok[1][0] * H4 + j];
    float xzn2 = g_table[(size_t)sh_tok[2][0] * H4 + j];
    float xzn3 = g_table[(size_t)sh_tok[3][0] * H4 + j];

#pragma unroll 1
    for (int t = 0; t < TLEN; t++) {
        const float xz0 = xzn0, xz1 = xzn1, xz2 = xzn2, xz3 = xzn3;
        const int tn = (t < TLEN - 1) ? t + 1 : t;
        xzn0 = g_table[(size_t)sh_tok[0][tn] * H4 + j];
        xzn1 = g_table[(size_t)sh_tok[1][tn] * H4 + j];
        xzn2 = g_table[(size_t)sh_tok[2][tn] * H4 + j];
        xzn3 = g_table[(size_t)sh_tok[3][tn] * H4 + j];

        // z[s][j] = xz[s] + h[s] . Wr[:,j]  -- 4 batches, 2 packed accs each.
        // h reads are uniform across the CTA (broadcast, conflict-free).
        const ulonglong2* hb = reinterpret_cast<const ulonglong2*>(sh_h[t & 1][0]);
        unsigned long long A0 = 0ull, B0 = 0ull, A1 = 0ull, B1 = 0ull;
        unsigned long long A2 = 0ull, B2 = 0ull, A3 = 0ull, B3 = 0ull;
#pragma unroll
        for (int m = 0; m < 16; m++) {
            ulonglong2 p0 = hb[m];
            ulonglong2 p1 = hb[16 + m];
            ulonglong2 p2 = hb[32 + m];
            ulonglong2 p3 = hb[48 + m];
            const unsigned long long w0 = wr2[2 * m], w1 = wr2[2 * m + 1];
            FMA2(A0, p0.x, w0);
            FMA2(B0, p0.y, w1);
            FMA2(A1, p1.x, w0);
            FMA2(B1, p1.y, w1);
            FMA2(A2, p2.x, w0);
            FMA2(B2, p2.y, w1);
            FMA2(A3, p3.x, w0);
            FMA2(B3, p3.y, w1);
        }
        {
            unsigned long long r;
            float2 f;
            ADD2(r, A0, B0); f = unpack2(r); sh_z[0][j] = xz0 + f.x + f.y;
            ADD2(r, A1, B1); f = unpack2(r); sh_z[1][j] = xz1 + f.x + f.y;
            ADD2(r, A2, B2); f = unpack2(r); sh_z[2][j] = xz2 + f.x + f.y;
            ADD2(r, A3, B3); f = unpack2(r); sh_z[3][j] = xz3 + f.x + f.y;
        }
        __syncthreads();

        // gate phase: all 256 threads, one (batch, unit) each
        {
            const float zi = sh_z[su_s][su_u];
            const float zf = sh_z[su_s][su_u + HID];
            const float zg = sh_z[su_s][su_u + 2 * HID];
            const float zo = sh_z[su_s][su_u + 3 * HID];
            const float ig = sigf(zi);
            const float fg = sigf(zf);
            const float og = sigf(zo);
            const float gg = tanh_acc(zg);
            cst = fg * cst + ig * gg;
            sh_h[(t & 1) ^ 1][su_s][su_u] = og * tanh_acc(cst);
        }
        __syncthreads();
    }

    // final h in buffer 0 (last write at t=511 targets (511&1)^1 = 0)
    if (j < 4) {
        const int s = j;
        float l0 = bd[0], l1 = bd[1], l2 = bd[2];
#pragma unroll 8
        for (int u = 0; u < HID; u++) {
            const float h = sh_h[0][s][u];
            l0 += h * Wd[u * NCLS + 0];
            l1 += h * Wd[u * NCLS + 1];
            l2 += h * Wd[u * NCLS + 2];
        }
        const float m  = fmaxf(l0, fmaxf(l1, l2));
        const float e0 = __expf(l0 - m);
        const float e1 = __expf(l1 - m);
        const float e2 = __expf(l2 - m);
        const float inv = __fdividef(1.0f, e0 + e1 + e2);
        float* o = out + (size_t)(b0 + s) * NCLS;
        o[0] = e0 * inv;
        o[1] = e1 * inv;
        o[2] = e2 * inv;
    }
}

extern "C" void kernel_launch(void* const* d_in, const int* in_sizes, int n_in,
                              void* d_out, int out_size)
{
    const int*   tokens = (const int*)  d_in[0];
    const float* emb    = (const float*)d_in[1];
    const float* Wk     = (const float*)d_in[2];
    const float* Wr     = (const float*)d_in[3];
    const float* b      = (const float*)d_in[4];
    const float* Wd     = (const float*)d_in[5];
    const float* bd     = (const float*)d_in[6];
    float* out = (float*)d_out;

    table_kernel<<<(VOCAB + 63) / 64, 256>>>(emb, Wk, b);
    lstm_kernel<<<BSZ / 4, 256>>>(tokens, Wr, Wd, bd, out);
}

// round 6
// speedup vs baseline: 1.3972x; 1.1621x over previous
#include <cuda_runtime.h>
#include <cstdint>

#define VOCAB 50000
#define EMB   32
#define HID   64
#define H4    256
#define NCLS  3
#define BSZ   512
#define TLEN  512

// 51.2MB scratch: precomputed emb @ Wk + bias, per vocab entry (256 floats each)
__device__ float g_table[(size_t)VOCAB * H4];

// ---------- packed f32x2 helpers (sm_103a FFMA2 path, PTX-only) ----------
__device__ __forceinline__ unsigned long long pack2(float lo, float hi) {
    unsigned long long r;
    asm("mov.b64 %0, {%1, %2};" : "=l"(r) : "f"(lo), "f"(hi));
    return r;
}
__device__ __forceinline__ float2 unpack2(unsigned long long v) {
    float2 f;
    asm("mov.b64 {%0, %1}, %2;" : "=f"(f.x), "=f"(f.y) : "l"(v));
    return f;
}
#define FMA2(acc, a, b) \
    asm("fma.rn.f32x2 %0, %1, %2, %0;" : "+l"(acc) : "l"(a), "l"(b))
#define ADD2(d, a, b) \
    asm("add.rn.f32x2 %0, %1, %2;" : "=l"(d) : "l"(a), "l"(b))

__device__ __forceinline__ float ex2a(float x) {
    float r;
    asm("ex2.approx.ftz.f32 %0, %1;" : "=f"(r) : "f"(x));
    return r;
}
__device__ __forceinline__ float rcpa(float x) {
    float r;
    asm("rcp.approx.ftz.f32 %0, %1;" : "=f"(r) : "f"(x));
    return r;
}
#define LOG2E 1.4426950408889634f
// sigmoid: 1/(1+2^(-log2e*x)); saturates correctly at +-inf under ftz
__device__ __forceinline__ float sigf(float x) {
    return rcpa(1.0f + ex2a(-LOG2E * x));
}
// tanh(x) = 2*sigmoid(2x) - 1
__device__ __forceinline__ float tanhf_fast(float x) {
    return fmaf(2.0f, rcpa(1.0f + ex2a(-2.0f * LOG2E * x)), -1.0f);
}

// ---------- kernel 1: g_table[v][j] = sum_e emb[v][e]*Wk[e][j] + b[j] ----------
__global__ __launch_bounds__(256) void table_kernel(
    const float* __restrict__ emb, const float* __restrict__ Wk,
    const float* __restrict__ bias)
{
    __shared__ __align__(16) float sh_e[64 * EMB];
    const int j  = threadIdx.x;
    const int v0 = blockIdx.x * 64;

    unsigned long long wk2[16];
#pragma unroll
    for (int m = 0; m < 16; m++)
        wk2[m] = pack2(Wk[(2 * m) * H4 + j], Wk[(2 * m + 1) * H4 + j]);
    const float bj = bias[j];

    const int nrows = min(64, VOCAB - v0);
    const float4* src = reinterpret_cast<const float4*>(emb + (size_t)v0 * EMB);
    float4* dst = reinterpret_cast<float4*>(sh_e);
    for (int i = j; i < nrows * (EMB / 4); i += 256) dst[i] = src[i];
    __syncthreads();

    for (int r = 0; r < nrows; r++) {
        const ulonglong2* ev = reinterpret_cast<const ulonglong2*>(sh_e + r * EMB);
        unsigned long long a0 = 0ull, a1 = 0ull;
#pragma unroll
        for (int m = 0; m < 4; m++) {
            ulonglong2 p = ev[2 * m];
            ulonglong2 q = ev[2 * m + 1];
            FMA2(a0, p.x, wk2[4 * m + 0]);
            FMA2(a1, p.y, wk2[4 * m + 1]);
            FMA2(a0, q.x, wk2[4 * m + 2]);
            FMA2(a1, q.y, wk2[4 * m + 3]);
        }
        unsigned long long s;
        ADD2(s, a0, a1);
        float2 f = unpack2(s);
        g_table[(size_t)(v0 + r) * H4 + j] = bj + f.x + f.y;
    }
}

// ---------- kernel 2: recurrent LSTM, 2 batch rows per CTA, occ 2 ----------
// Thread j owns gate-column j for both batches (64 FMA2/step). Gate phase:
// threads 0..127 handle (s=j>>6, u=j&63). h double-buffered; 2 barriers/step.
// Odd-bid CTAs delay ~700cyc at start to anti-phase co-resident CTA pairs.
__global__ __launch_bounds__(256, 2) void lstm_kernel(
    const int*   __restrict__ tokens,
    const float* __restrict__ Wr,
    const float* __restrict__ Wd,
    const float* __restrict__ bd,
    float*       __restrict__ out)
{
    __shared__ __align__(16) float sh_h[2][2][HID];  // [buf][batch][unit]
    __shared__ float sh_z[2][H4];
    __shared__ int   sh_tok[2][TLEN];

    const int j    = threadIdx.x;     // gate column 0..255
    const int su_s = j >> 6;          // gate-phase batch (j<128)
    const int su_u = j & (HID - 1);   // gate-phase unit
    const int b0   = blockIdx.x * 2;

    // stage this CTA's 2 token rows
    for (int i = j; i < 2 * TLEN; i += 256) {
        int s = i >> 9, t = i & (TLEN - 1);
        sh_tok[s][t] = tokens[(size_t)(b0 + s) * TLEN + t];
    }

    // Wr column j, packed over k: wr2[m] = (Wr[2m][j], Wr[2m+1][j])
    unsigned long long wr2[32];
#pragma unroll
    for (int m = 0; m < 32; m++)
        wr2[m] = pack2(Wr[(2 * m) * H4 + j], Wr[(2 * m + 1) * H4 + j]);

    if (j < 2 * HID) sh_h[0][su_s][su_u] = 0.0f;
    float cst = 0.0f;  // cell state for (su_s, su_u); valid for j<128

    // anti-phase stagger: odd CTAs burn ~700 cyc in a serial dependent chain
    if (blockIdx.x & 1) {
        float d = (float)(sh_tok[0][0] & 1);  // 0 or 1, data-dependent
        const float z0 = 0.0f;
#pragma unroll 1
        for (int i = 0; i < 128; i++)
            asm("add.f32 %0, %0, %1;" : "+f"(d) : "f"(z0));
        if (d > 2.0f) sh_z[0][0] = d;  // never true; keeps the chain alive
    }
    __syncthreads();

    // prefetch xz for t=0 (table is L2-resident)
    float xzn0 = g_table[(size_t)sh_tok[0][0] * H4 + j];
    float xzn1 = g_table[(size_t)sh_tok[1][0] * H4 + j];

#pragma unroll 1
    for (int t = 0; t < TLEN; t++) {
        const float xz0 = xzn0, xz1 = xzn1;
        const int tn = (t < TLEN - 1) ? t + 1 : t;
        xzn0 = g_table[(size_t)sh_tok[0][tn] * H4 + j];
        xzn1 = g_table[(size_t)sh_tok[1][tn] * H4 + j];

        // z[s][j] = xz[s] + h[s] . Wr[:,j]  (4 packed chains per batch)
        const float* hb = sh_h[t & 1][0];
        const ulonglong2* h0 = reinterpret_cast<const ulonglong2*>(hb);
        const ulonglong2* h1 = reinterpret_cast<const ulonglong2*>(hb + HID);
        unsigned long long a0 = 0ull, a1 = 0ull, a2 = 0ull, a3 = 0ull;
        unsigned long long c0 = 0ull, c1 = 0ull, c2 = 0ull, c3 = 0ull;
#pragma unroll
        for (int m = 0; m < 8; m++) {
            ulonglong2 p0 = h0[2 * m];
            ulonglong2 q0 = h0[2 * m + 1];
            ulonglong2 p1 = h1[2 * m];
            ulonglong2 q1 = h1[2 * m + 1];
            const unsigned long long w0 = wr2[4 * m + 0];
            const unsigned long long w1 = wr2[4 * m + 1];
            const unsigned long long w2 = wr2[4 * m + 2];
            const unsigned long long w3 = wr2[4 * m + 3];
            FMA2(a0, p0.x, w0);
            FMA2(a1, p0.y, w1);
            FMA2(a2, q0.x, w2);
            FMA2(a3, q0.y, w3);
            FMA2(c0, p1.x, w0);
            FMA2(c1, p1.y, w1);
            FMA2(c2, q1.x, w2);
            FMA2(c3, q1.y, w3);
        }
        {
            unsigned long long r0, r1;
            float2 f;
            ADD2(r0, a0, a1);
            ADD2(r1, a2, a3);
            ADD2(r0, r0, r1);
            f = unpack2(r0);
            sh_z[0][j] = xz0 + f.x + f.y;
            ADD2(r0, c0, c1);
            ADD2(r1, c2, c3);
            ADD2(r0, r0, r1);
            f = unpack2(r0);
            sh_z[1][j] = xz1 + f.x + f.y;
        }
        __syncthreads();

        // gate phase: threads 0..127, one (batch, unit) each
        if (j < 2 * HID) {
            const float zi = sh_z[su_s][su_u];
            const float zf = sh_z[su_s][su_u + HID];
            const float zg = sh_z[su_s][su_u + 2 * HID];
            const float zo = sh_z[su_s][su_u + 3 * HID];
            const float ig = sigf(zi);
            const float fg = sigf(zf);
            const float og = sigf(zo);
            const float gg = tanhf_fast(zg);
            cst = fmaf(fg, cst, ig * gg);
            sh_h[(t & 1) ^ 1][su_s][su_u] = og * tanhf_fast(cst);
        }
        __syncthreads();
    }

    // final h in buffer 0 (last write at t=511 targets (511&1)^1 = 0)
    if (j < 2) {
        const int s = j;
        float l0 = bd[0], l1 = bd[1], l2 = bd[2];
#pragma unroll 8
        for (int u = 0; u < HID; u++) {
            const float h = sh_h[0][s][u];
            l0 += h * Wd[u * NCLS + 0];
            l1 += h * Wd[u * NCLS + 1];
            l2 += h * Wd[u * NCLS + 2];
        }
        const float m  = fmaxf(l0, fmaxf(l1, l2));
        const float e0 = ex2a(LOG2E * (l0 - m));
        const float e1 = ex2a(LOG2E * (l1 - m));
        const float e2 = ex2a(LOG2E * (l2 - m));
        const float inv = rcpa(e0 + e1 + e2);
        float* o = out + (size_t)(b0 + s) * NCLS;
        o[0] = e0 * inv;
        o[1] = e1 * inv;
        o[2] = e2 * inv;
    }
}

extern "C" void kernel_launch(void* const* d_in, const int* in_sizes, int n_in,
                              void* d_out, int out_size)
{
    const int*   tokens = (const int*)  d_in[0];
    const float* emb    = (const float*)d_in[1];
    const float* Wk     = (const float*)d_in[2];
    const float* Wr     = (const float*)d_in[3];
    const float* b      = (const float*)d_in[4];
    const float* Wd     = (const float*)d_in[5];
    const float* bd     = (const float*)d_in[6];
    float* out = (float*)d_out;

    table_kernel<<<(VOCAB + 63) / 64, 256>>>(emb, Wk, b);
    lstm_kernel<<<BSZ / 2, 256>>>(tokens, Wr, Wd, bd, out);
}